// round 4
// baseline (speedup 1.0000x reference)
#include <cuda_runtime.h>
#include <cuda_bf16.h>
#include <cstdint>
#include <math.h>

#define NN 8192
#define DD 128
#define TILE 128
#define NB (NN / TILE)            // 64 block-rows
#define NTRI (NB * (NB + 1) / 2)  // 2080 triangular tiles

#define LDT 272                   // GEMM smem tile row stride (bytes)
#define TILE_BYTES (TILE * LDT)   // 34816
#define OFF_A 0
#define OFF_B TILE_BYTES
#define OFF_W1 (2 * TILE_BYTES)   // 69632: W stage block 1 (128 x 132 floats)
#define WST 528                   // W stage row stride bytes (132 floats)
#define WST_BYTES (TILE * WST)    // 67584
#define OFF_W2 (OFF_W1 + WST_BYTES)
#define SMEM_DYN (OFF_W2 + WST_BYTES)   // 204800 (< 227KB opt-in)

__device__ double g_sumDW;
__device__ double g_sumW;
__device__ int    g_maxSq;        // float bits; all >= 0 so int-max works
__device__ float  g_norms[NN];
__device__ __nv_bfloat16 g_ehi[NN * DD];
__device__ __nv_bfloat16 g_elo[NN * DD];

// ---------------- helpers ----------------
__device__ __forceinline__ uint32_t smem_u32(const void* p) {
    uint32_t a;
    asm("{ .reg .u64 t; cvta.to.shared.u64 t, %1; cvt.u32.u64 %0, t; }"
        : "=r"(a) : "l"(p));
    return a;
}
__device__ __forceinline__ void ldsm_x4(uint32_t& r0, uint32_t& r1,
                                        uint32_t& r2, uint32_t& r3, uint32_t a) {
    asm volatile("ldmatrix.sync.aligned.m8n8.x4.shared.b16 {%0,%1,%2,%3}, [%4];"
                 : "=r"(r0), "=r"(r1), "=r"(r2), "=r"(r3) : "r"(a));
}
__device__ __forceinline__ void mma16816(float* d, const uint32_t* a,
                                         const uint32_t* b) {
    asm volatile(
        "mma.sync.aligned.m16n8k16.row.col.f32.bf16.bf16.f32 "
        "{%0,%1,%2,%3}, {%4,%5,%6,%7}, {%8,%9}, {%0,%1,%2,%3};"
        : "+f"(d[0]), "+f"(d[1]), "+f"(d[2]), "+f"(d[3])
        : "r"(a[0]), "r"(a[1]), "r"(a[2]), "r"(a[3]), "r"(b[0]), "r"(b[1]));
}
__device__ __forceinline__ void cp16(uint32_t dst, const void* src) {
    asm volatile("cp.async.cg.shared.global [%0], [%1], 16;"
                 :: "r"(dst), "l"(src) : "memory");
}

// ---------------- prep kernels ----------------
__global__ void init_kernel() {
    g_sumDW = 0.0;
    g_sumW  = 0.0;
    g_maxSq = 0;
}

__global__ __launch_bounds__(256) void convert_kernel(const float* __restrict__ emb) {
    int idx = blockIdx.x * 256 + threadIdx.x;
    float x = emb[idx];
    __nv_bfloat16 hi = __float2bfloat16(x);
    g_ehi[idx] = hi;
    g_elo[idx] = __float2bfloat16(x - __bfloat162float(hi));
}

__global__ __launch_bounds__(256) void norm_kernel(const float* __restrict__ emb) {
    int row = blockIdx.x * 256 + threadIdx.x;
    const float4* p = reinterpret_cast<const float4*>(emb) + (size_t)row * (DD / 4);
    float s = 0.f;
#pragma unroll
    for (int i = 0; i < DD / 4; i++) {
        float4 v = p[i];
        s += v.x * v.x + v.y * v.y + v.z * v.z + v.w * v.w;
    }
    g_norms[row] = s;
}

// ---------------- main kernel ----------------
__global__ __launch_bounds__(512, 1) void main_kernel(const float* __restrict__ W) {
    extern __shared__ char sm[];
    __shared__ float nI[TILE];
    __shared__ float nJ[TILE];
    __shared__ float redDW[16], redW[16], redM[16];

    const int tid = threadIdx.x;
    const int wid = tid >> 5;
    const int lane = tid & 31;

    // ---- triangular tile decode: bi <= bj ----
    int t = blockIdx.x;
    float ff = 2.0f * NB + 1.0f;
    int bi = (int)((ff - sqrtf(ff * ff - 8.0f * (float)t)) * 0.5f);
    if (bi < 0) bi = 0;
    if (bi > NB - 1) bi = NB - 1;
#define SFUN(b) ((b) * NB - (b) * ((b) - 1) / 2)
    while (bi > 0 && SFUN(bi) > t) bi--;
    while (SFUN(bi + 1) <= t) bi++;
    const int bj = bi + (t - SFUN(bi));
    const int gi0 = bi * TILE;
    const int gj0 = bj * TILE;
    const bool diag = (bi == bj);

    if (tid < TILE)            nI[tid] = g_norms[gi0 + tid];
    else if (tid < 2 * TILE)   nJ[tid - TILE] = g_norms[gj0 + tid - TILE];

    const uint32_t smbase = smem_u32(sm);
    const uint32_t smA = smbase + OFF_A;
    const uint32_t smB = smbase + OFF_B;

    // ---- hi-chunk tile loads (LDG/STS; emb arrays are L2-resident, 4MB) ----
    {
        const uint4* src = (const uint4*)g_ehi;
#pragma unroll
        for (int it = 0; it < 4; it++) {
            int idx = it * 512 + tid;
            int r = idx >> 4, c = idx & 15;
            *(uint4*)(sm + OFF_A + r * LDT + c * 16) = src[(size_t)(gi0 + r) * 16 + c];
            *(uint4*)(sm + OFF_B + r * LDT + c * 16) = src[(size_t)(gj0 + r) * 16 + c];
        }
    }

    // ---- W prefetch via cp.async into padded smem stage (overlaps GEMM) ----
    {
        const char* wb = (const char*)W;
#pragma unroll
        for (int q = 0; q < 8; q++) {
            int idx = q * 512 + tid;
            int r = idx >> 5, c16 = idx & 31;
            cp16(smbase + OFF_W1 + r * WST + c16 * 16,
                 wb + ((size_t)(gi0 + r) * NN + gj0) * 4 + c16 * 16);
        }
        if (!diag) {
#pragma unroll
            for (int q = 0; q < 8; q++) {
                int idx = q * 512 + tid;
                int r = idx >> 5, c16 = idx & 31;
                cp16(smbase + OFF_W2 + r * WST + c16 * 16,
                     wb + ((size_t)(gj0 + r) * NN + gi0) * 4 + c16 * 16);
            }
        }
        asm volatile("cp.async.commit_group;" ::: "memory");
    }
    __syncthreads();

    // ---- GEMM: K=256 as two 128-chunks (hi then lo); 16 warps, 32x32 each ----
    const int wr = wid & 3;
    const int wc = wid >> 2;
    float acc[2][4][4];
#pragma unroll
    for (int mi = 0; mi < 2; mi++)
#pragma unroll
        for (int ni = 0; ni < 4; ni++)
#pragma unroll
            for (int q = 0; q < 4; q++) acc[mi][ni][q] = 0.f;

    const uint32_t a_row = (lane & 15);
    const uint32_t a_koff = ((lane >> 4) << 3) * 2;
    const uint32_t b_row = (lane & 7) + ((lane >> 4) << 3);
    const uint32_t b_koff = (((lane >> 3) & 1) << 3) * 2;

    for (int kc = 0; kc < 2; kc++) {
        if (kc) {
            __syncthreads();   // hi chunk consumed
            const uint4* src = (const uint4*)g_elo;
#pragma unroll
            for (int it = 0; it < 4; it++) {
                int idx = it * 512 + tid;
                int r = idx >> 4, c = idx & 15;
                *(uint4*)(sm + OFF_A + r * LDT + c * 16) = src[(size_t)(gi0 + r) * 16 + c];
                *(uint4*)(sm + OFF_B + r * LDT + c * 16) = src[(size_t)(gj0 + r) * 16 + c];
            }
        }
        __syncthreads();

#pragma unroll
        for (int ks = 0; ks < 8; ks++) {
            const uint32_t k0b = ks * 32;
            uint32_t af[2][4];
#pragma unroll
            for (int mi = 0; mi < 2; mi++) {
                uint32_t addr = smA + (wr * 32 + mi * 16 + a_row) * LDT + k0b + a_koff;
                ldsm_x4(af[mi][0], af[mi][1], af[mi][2], af[mi][3], addr);
            }
            uint32_t bf[4][2];
#pragma unroll
            for (int nq = 0; nq < 2; nq++) {
                uint32_t addr = smB + (wc * 32 + nq * 16 + b_row) * LDT + k0b + b_koff;
                uint32_t r0, r1, r2, r3;
                ldsm_x4(r0, r1, r2, r3, addr);
                bf[nq * 2][0] = r0; bf[nq * 2][1] = r1;
                bf[nq * 2 + 1][0] = r2; bf[nq * 2 + 1][1] = r3;
            }
#pragma unroll
            for (int mi = 0; mi < 2; mi++)
#pragma unroll
                for (int ni = 0; ni < 4; ni++)
                    mma16816(acc[mi][ni], af[mi], bf[ni]);
        }
    }

    __syncthreads();                // LDSM done; overlay dist on tile region
    float* dist = (float*)sm;       // [128][129]

    float maxsq = 0.f;
    const int crow = lane >> 2;
    const int ccol = (lane & 3) * 2;
#pragma unroll
    for (int mi = 0; mi < 2; mi++) {
#pragma unroll
        for (int ni = 0; ni < 4; ni++) {
#pragma unroll
            for (int h = 0; h < 2; h++) {
                int r = wr * 32 + mi * 16 + crow + h * 8;
                int c = wc * 32 + ni * 8 + ccol;
                float nn_ = nI[r];
                float s0 = fmaxf(nn_ + nJ[c]     - 2.f * acc[mi][ni][2 * h],     0.f);
                float s1 = fmaxf(nn_ + nJ[c + 1] - 2.f * acc[mi][ni][2 * h + 1], 0.f);
                maxsq = fmaxf(maxsq, fmaxf(s0, s1));
                dist[r * 129 + c]     = sqrtf(s0);
                dist[r * 129 + c + 1] = sqrtf(s1);
            }
        }
    }

    asm volatile("cp.async.wait_group 0;" ::: "memory");
    __syncthreads();                // dist visible + W stage complete

    // ---- W consume from smem stage ----
    const int c4 = tid & 31;        // float4 column
    const int r0 = tid >> 5;        // 0..15
    float sDW = 0.f, sW = 0.f;
    const float* wst1 = (const float*)(sm + OFF_W1);
    const float* wst2 = (const float*)(sm + OFF_W2);
#pragma unroll
    for (int p = 0; p < 8; p++) {
        int r = r0 + 16 * p;
        float4 w1 = *(const float4*)(wst1 + r * 132 + c4 * 4);
        const float* dr = dist + r * 129 + c4 * 4;
        sDW += dr[0] * w1.x + dr[1] * w1.y + dr[2] * w1.z + dr[3] * w1.w;
        sW += w1.x + w1.y + w1.z + w1.w;
    }
    if (!diag) {
#pragma unroll
        for (int p = 0; p < 8; p++) {
            int r = r0 + 16 * p;
            float4 w2 = *(const float4*)(wst2 + r * 132 + c4 * 4);
            int c = c4 * 4;
            sDW += dist[(c + 0) * 129 + r] * w2.x;
            sDW += dist[(c + 1) * 129 + r] * w2.y;
            sDW += dist[(c + 2) * 129 + r] * w2.z;
            sDW += dist[(c + 3) * 129 + r] * w2.w;
            sW += w2.x + w2.y + w2.z + w2.w;
        }
    }

    // ---- reductions ----
#pragma unroll
    for (int o = 16; o > 0; o >>= 1) {
        sDW += __shfl_xor_sync(0xFFFFFFFF, sDW, o);
        sW  += __shfl_xor_sync(0xFFFFFFFF, sW, o);
        maxsq = fmaxf(maxsq, __shfl_xor_sync(0xFFFFFFFF, maxsq, o));
    }
    if (lane == 0) { redDW[wid] = sDW; redW[wid] = sW; redM[wid] = maxsq; }
    __syncthreads();
    if (tid == 0) {
        double a = 0.0, b = 0.0;
        float m = 0.f;
#pragma unroll
        for (int w = 0; w < 16; w++) {
            a += (double)redDW[w];
            b += (double)redW[w];
            m = fmaxf(m, redM[w]);
        }
        atomicAdd(&g_sumDW, a);
        atomicAdd(&g_sumW, b);
        atomicMax(&g_maxSq, __float_as_int(m));
    }
}

// ---------------- finalize ----------------
__global__ void finalize_kernel(float* out) {
    double maxd = sqrt((double)__int_as_float(g_maxSq));
    double res = (g_sumW - g_sumDW / maxd) / ((double)NN * (double)NN);
    out[0] = (float)res;
}

extern "C" void kernel_launch(void* const* d_in, const int* in_sizes, int n_in,
                              void* d_out, int out_size) {
    const float* emb = (const float*)d_in[0];   // [8192, 128] fp32
    const float* W   = (const float*)d_in[1];   // [8192, 8192] fp32
    float* out = (float*)d_out;

    cudaFuncSetAttribute(main_kernel, cudaFuncAttributeMaxDynamicSharedMemorySize,
                         SMEM_DYN);

    init_kernel<<<1, 1>>>();
    convert_kernel<<<(NN * DD) / 256, 256>>>(emb);
    norm_kernel<<<NN / 256, 256>>>(emb);
    main_kernel<<<NTRI, 512, SMEM_DYN>>>(W);
    finalize_kernel<<<1, 1>>>(out);
}

// round 5
// speedup vs baseline: 1.1760x; 1.1760x over previous
#include <cuda_runtime.h>
#include <cuda_bf16.h>
#include <cstdint>
#include <math.h>

#define NN 8192
#define DD 128
#define TILE 128
#define NB (NN / TILE)            // 64 block-rows
#define NTRI (NB * (NB + 1) / 2)  // 2080 triangular tiles

#define LDT 272                   // GEMM smem tile row stride (bytes)
#define TILE_BYTES (TILE * LDT)   // 34816
#define OFF_A 0
#define OFF_B TILE_BYTES
#define OFF_RING (2 * TILE_BYTES) // 69632
#define CHUNK_BYTES 8192          // 16 rows x 128 floats
#define SMEM_DYN (OFF_RING + 4 * CHUNK_BYTES)   // 102400 -> 2 CTAs/SM

__device__ double g_sumDW;
__device__ double g_sumW;
__device__ int    g_maxSq;        // float bits; all >= 0 so int-max works
__device__ float  g_norms[NN];
__device__ __nv_bfloat16 g_ehi[NN * DD];
__device__ __nv_bfloat16 g_elo[NN * DD];

// ---------------- helpers ----------------
__device__ __forceinline__ uint32_t smem_u32(const void* p) {
    uint32_t a;
    asm("{ .reg .u64 t; cvta.to.shared.u64 t, %1; cvt.u32.u64 %0, t; }"
        : "=r"(a) : "l"(p));
    return a;
}
__device__ __forceinline__ void ldsm_x4(uint32_t& r0, uint32_t& r1,
                                        uint32_t& r2, uint32_t& r3, uint32_t a) {
    asm volatile("ldmatrix.sync.aligned.m8n8.x4.shared.b16 {%0,%1,%2,%3}, [%4];"
                 : "=r"(r0), "=r"(r1), "=r"(r2), "=r"(r3) : "r"(a));
}
__device__ __forceinline__ void mma16816(float* d, const uint32_t* a,
                                         const uint32_t* b) {
    asm volatile(
        "mma.sync.aligned.m16n8k16.row.col.f32.bf16.bf16.f32 "
        "{%0,%1,%2,%3}, {%4,%5,%6,%7}, {%8,%9}, {%0,%1,%2,%3};"
        : "+f"(d[0]), "+f"(d[1]), "+f"(d[2]), "+f"(d[3])
        : "r"(a[0]), "r"(a[1]), "r"(a[2]), "r"(a[3]), "r"(b[0]), "r"(b[1]));
}
__device__ __forceinline__ void cp16(uint32_t dst, const void* src) {
    asm volatile("cp.async.cg.shared.global [%0], [%1], 16;"
                 :: "r"(dst), "l"(src) : "memory");
}
// XOR-swizzled dist word index: conflict-free for row AND column access
__device__ __forceinline__ uint32_t dword(int r, int c) {
    return (uint32_t)(((r >> 5) * 4 + (c >> 5)) * 1024
                      + (r & 31) * 32 + ((c & 31) ^ (r & 31)));
}

// ---------------- prep kernels ----------------
__global__ void init_kernel() {
    g_sumDW = 0.0;
    g_sumW  = 0.0;
    g_maxSq = 0;
}

__global__ __launch_bounds__(256) void convert_kernel(const float* __restrict__ emb) {
    int idx = blockIdx.x * 256 + threadIdx.x;
    float x = emb[idx];
    __nv_bfloat16 hi = __float2bfloat16(x);
    g_ehi[idx] = hi;
    g_elo[idx] = __float2bfloat16(x - __bfloat162float(hi));
}

__global__ __launch_bounds__(256) void norm_kernel(const float* __restrict__ emb) {
    int row = blockIdx.x * 256 + threadIdx.x;
    const float4* p = reinterpret_cast<const float4*>(emb) + (size_t)row * (DD / 4);
    float s = 0.f;
#pragma unroll
    for (int i = 0; i < DD / 4; i++) {
        float4 v = p[i];
        s += v.x * v.x + v.y * v.y + v.z * v.z + v.w * v.w;
    }
    g_norms[row] = s;
}

// ---------------- main kernel ----------------
__global__ __launch_bounds__(256, 2) void main_kernel(const float* __restrict__ W) {
    extern __shared__ char sm[];
    __shared__ float nI[TILE];
    __shared__ float nJ[TILE];
    __shared__ float redDW[8], redW[8], redM[8];

    const int tid = threadIdx.x;
    const int wid = tid >> 5;
    const int lane = tid & 31;

    // ---- triangular tile decode: bi <= bj ----
    int t = blockIdx.x;
    float ff = 2.0f * NB + 1.0f;
    int bi = (int)((ff - sqrtf(ff * ff - 8.0f * (float)t)) * 0.5f);
    if (bi < 0) bi = 0;
    if (bi > NB - 1) bi = NB - 1;
#define SFUN(b) ((b) * NB - (b) * ((b) - 1) / 2)
    while (bi > 0 && SFUN(bi) > t) bi--;
    while (SFUN(bi + 1) <= t) bi++;
    const int bj = bi + (t - SFUN(bi));
    const int gi0 = bi * TILE;
    const int gj0 = bj * TILE;
    const bool diag = (bi == bj);
    const int nchunks = diag ? 8 : 16;

    const uint32_t smbase = smem_u32(sm);
    const uint32_t smA = smbase + OFF_A;
    const uint32_t smB = smbase + OFF_B;

    // chunk q: q<8 -> W[I-block rows, J cols]; q>=8 -> W[J-block rows, I cols]
    auto issue_chunk = [&](int q) {
        const int s = q & 3;
        const int srcR = ((q >= 8) ? gj0 : gi0) + (q & 7) * 16;
        const int colB = (q >= 8) ? gi0 : gj0;
        const int jr = tid >> 4, c16 = tid & 15;
        const char* src = (const char*)W + ((size_t)(srcR + jr) * NN + colB) * 4;
        uint32_t dst = smbase + OFF_RING + s * CHUNK_BYTES + jr * 512;
        cp16(dst + c16 * 16, src + (size_t)c16 * 16);
        cp16(dst + (c16 + 16) * 16, src + (size_t)(c16 + 16) * 16);
    };

    // ---- prologue: 3 W chunks in flight before GEMM starts ----
    issue_chunk(0);
    asm volatile("cp.async.commit_group;" ::: "memory");
    issue_chunk(1);
    asm volatile("cp.async.commit_group;" ::: "memory");
    issue_chunk(2);
    asm volatile("cp.async.commit_group;" ::: "memory");

    if (tid < TILE) nI[tid] = g_norms[gi0 + tid];
    else            nJ[tid - TILE] = g_norms[gj0 + tid - TILE];

    // ---- GEMM: K=256 as two 128-chunks (hi then lo); 8 warps, 32x64 each ----
    const int wm = wid & 3;
    const int wn = wid >> 2;
    float acc[2][8][4];
#pragma unroll
    for (int mi = 0; mi < 2; mi++)
#pragma unroll
        for (int ni = 0; ni < 8; ni++)
#pragma unroll
            for (int q = 0; q < 4; q++) acc[mi][ni][q] = 0.f;

    const uint32_t a_row = (lane & 15);
    const uint32_t a_koff = ((lane >> 4) << 3) * 2;
    const uint32_t b_row = (lane & 7) + ((lane >> 4) << 3);
    const uint32_t b_koff = (((lane >> 3) & 1) << 3) * 2;

    for (int kc = 0; kc < 2; kc++) {
        const uint4* src = (const uint4*)(kc ? g_elo : g_ehi);
        if (kc) __syncthreads();       // previous chunk fully consumed
#pragma unroll
        for (int it = 0; it < 8; it++) {
            int idx = it * 256 + tid;
            int r = idx >> 4, c = idx & 15;
            *(uint4*)(sm + OFF_A + r * LDT + c * 16) = src[(size_t)(gi0 + r) * 16 + c];
            *(uint4*)(sm + OFF_B + r * LDT + c * 16) = src[(size_t)(gj0 + r) * 16 + c];
        }
        __syncthreads();

#pragma unroll
        for (int ks = 0; ks < 8; ks++) {
            const uint32_t k0b = ks * 32;
            uint32_t af[2][4];
#pragma unroll
            for (int mi = 0; mi < 2; mi++) {
                uint32_t addr = smA + (wm * 32 + mi * 16 + a_row) * LDT + k0b + a_koff;
                ldsm_x4(af[mi][0], af[mi][1], af[mi][2], af[mi][3], addr);
            }
            uint32_t bf[8][2];
#pragma unroll
            for (int nq = 0; nq < 4; nq++) {
                uint32_t addr = smB + (wn * 64 + nq * 16 + b_row) * LDT + k0b + b_koff;
                uint32_t r0, r1, r2, r3;
                ldsm_x4(r0, r1, r2, r3, addr);
                bf[nq * 2][0] = r0; bf[nq * 2][1] = r1;
                bf[nq * 2 + 1][0] = r2; bf[nq * 2 + 1][1] = r3;
            }
#pragma unroll
            for (int mi = 0; mi < 2; mi++)
#pragma unroll
                for (int ni = 0; ni < 8; ni++)
                    mma16816(acc[mi][ni], af[mi], bf[ni]);
        }
    }

    __syncthreads();                   // tiles consumed; overlay dist
    float* dist = (float*)sm;          // swizzled 128x128

    float maxsq = 0.f;
    const int crow = lane >> 2;
    const int ccol = (lane & 3) * 2;
#pragma unroll
    for (int mi = 0; mi < 2; mi++) {
#pragma unroll
        for (int ni = 0; ni < 8; ni++) {
#pragma unroll
            for (int h = 0; h < 2; h++) {
                int r = wm * 32 + mi * 16 + crow + h * 8;
                int c = wn * 64 + ni * 8 + ccol;
                float nn_ = nI[r];
                float s0 = fmaxf(nn_ + nJ[c]     - 2.f * acc[mi][ni][2 * h],     0.f);
                float s1 = fmaxf(nn_ + nJ[c + 1] - 2.f * acc[mi][ni][2 * h + 1], 0.f);
                maxsq = fmaxf(maxsq, fmaxf(s0, s1));
                dist[dword(r, c)]     = sqrtf(s0);
                dist[dword(r, c + 1)] = sqrtf(s1);
            }
        }
    }
    __syncthreads();                   // dist visible to all warps

    // ---- W consume: ring of chunks, 3 in flight, conflict-free LDS ----
    float sDW = 0.f, sW = 0.f;
    const int jr0 = wid * 2;           // warp handles rows {2w, 2w+1} of chunk
    for (int q = 0; q < nchunks; q++) {
        asm volatile("cp.async.wait_group 2;" ::: "memory");
        __syncthreads();               // chunk q fully landed (all threads)
        const float* stg = (const float*)(sm + OFF_RING + (q & 3) * CHUNK_BYTES);
        const int jbase = (q & 7) * 16;
        if (q < 8) {                   // W[I,J]: dist(row, col)
#pragma unroll
            for (int rr = 0; rr < 2; rr++) {
                int jr = jr0 + rr;
                int r = jbase + jr;
#pragma unroll
                for (int u = 0; u < 4; u++) {
                    int c = lane + 32 * u;
                    float w = stg[jr * 128 + c];
                    sDW += dist[dword(r, c)] * w;
                    sW += w;
                }
            }
        } else {                       // W[J,I]: dist(col, row) — swizzle keeps it conflict-free
#pragma unroll
            for (int rr = 0; rr < 2; rr++) {
                int jr = jr0 + rr;
                int jl = jbase + jr;
#pragma unroll
                for (int u = 0; u < 4; u++) {
                    int c = lane + 32 * u;
                    float w = stg[jr * 128 + c];
                    sDW += dist[dword(c, jl)] * w;
                    sW += w;
                }
            }
        }
        if (q + 3 < nchunks) issue_chunk(q + 3);
        asm volatile("cp.async.commit_group;" ::: "memory");  // empty group at tail keeps count
    }

    // ---- reductions ----
#pragma unroll
    for (int o = 16; o > 0; o >>= 1) {
        sDW += __shfl_xor_sync(0xFFFFFFFF, sDW, o);
        sW  += __shfl_xor_sync(0xFFFFFFFF, sW, o);
        maxsq = fmaxf(maxsq, __shfl_xor_sync(0xFFFFFFFF, maxsq, o));
    }
    if (lane == 0) { redDW[wid] = sDW; redW[wid] = sW; redM[wid] = maxsq; }
    __syncthreads();
    if (tid == 0) {
        double a = 0.0, b = 0.0;
        float m = 0.f;
#pragma unroll
        for (int w = 0; w < 8; w++) {
            a += (double)redDW[w];
            b += (double)redW[w];
            m = fmaxf(m, redM[w]);
        }
        atomicAdd(&g_sumDW, a);
        atomicAdd(&g_sumW, b);
        atomicMax(&g_maxSq, __float_as_int(m));
    }
}

// ---------------- finalize ----------------
__global__ void finalize_kernel(float* out) {
    double maxd = sqrt((double)__int_as_float(g_maxSq));
    double res = (g_sumW - g_sumDW / maxd) / ((double)NN * (double)NN);
    out[0] = (float)res;
}

extern "C" void kernel_launch(void* const* d_in, const int* in_sizes, int n_in,
                              void* d_out, int out_size) {
    const float* emb = (const float*)d_in[0];   // [8192, 128] fp32
    const float* W   = (const float*)d_in[1];   // [8192, 8192] fp32
    float* out = (float*)d_out;

    cudaFuncSetAttribute(main_kernel, cudaFuncAttributeMaxDynamicSharedMemorySize,
                         SMEM_DYN);

    init_kernel<<<1, 1>>>();
    convert_kernel<<<(NN * DD) / 256, 256>>>(emb);
    norm_kernel<<<NN / 256, 256>>>(emb);
    main_kernel<<<NTRI, 256, SMEM_DYN>>>(W);
    finalize_kernel<<<1, 1>>>(out);
}